// round 7
// baseline (speedup 1.0000x reference)
#include <cuda_runtime.h>
#include <cuda.h>
#include <cuda_bf16.h>
#include <cstdint>

// inputs:  [B=32, 56, 56, C=256] fp32 ; routing: [32, 4] fp32
// out[b,h,w,j] = inputs[b,h,w, argmax(routing[b])*64 + j]  -> [32,56,56,64]
//
// R7: full-TMA formulation. Input viewed as 2D tensor [rows=B*HW, 256 floats],
// row stride 1024B. Each CTA: one UTMALDG 2D tile (box [64 floats, 64 rows],
// coord_x = route*64) -> SMEM (packed, = output layout) -> one 16KB
// cp.async.bulk SMEM->GMEM. Bypasses the l1tex per-thread pipeline entirely.
// 1568 CTAs x 32 threads, ~16KB smem: whole grid resident in one wave.

namespace {
constexpr int B       = 32;
constexpr int HW      = 56 * 56;          // 3136 pixels per batch
constexpr int ROUTES  = 4;
constexpr int ROWS_PER_TILE = 64;         // pixels per CTA tile
constexpr int TILES_PER_B   = HW / ROWS_PER_TILE;   // 49 (exact)
constexpr int BLOCKS  = B * TILES_PER_B;            // 1568
constexpr int TILE_FLOATS = ROWS_PER_TILE * 64;     // 4096
constexpr int TILE_BYTES  = TILE_FLOATS * 4;        // 16384
}

__global__ __launch_bounds__(32)
void routing_tma_kernel(const __grid_constant__ CUtensorMap in_map,
                        const float* __restrict__ routing,
                        float* __restrict__ out)
{
    __shared__ alignas(1024) float tile[TILE_FLOATS];
    __shared__ alignas(8) uint64_t mbar;

    if (threadIdx.x != 0) return;   // single-thread CTA logic; TMA does the work

    const int t    = blockIdx.x;
    const int b    = t / TILES_PER_B;                    // const-div -> mulhi
    const int row0 = b * HW + (t - b * TILES_PER_B) * ROWS_PER_TILE;

    // argmax over 4 routing logits (strict '>' = first-max tie rule)
    const float* r = routing + b * ROUTES;
    float best = r[0];
    int route = 0;
#pragma unroll
    for (int k = 1; k < ROUTES; ++k) {
        float v = r[k];
        if (v > best) { best = v; route = k; }
    }

    const uint32_t smem_tile = (uint32_t)__cvta_generic_to_shared(tile);
    const uint32_t smem_mbar = (uint32_t)__cvta_generic_to_shared(&mbar);

    // init mbarrier, expect full tile, issue 2D TMA load
    asm volatile("mbarrier.init.shared.b64 [%0], %1;"
                 :: "r"(smem_mbar), "r"(1) : "memory");
    asm volatile("fence.proxy.async.shared::cta;" ::: "memory");
    asm volatile("mbarrier.arrive.expect_tx.shared.b64 _, [%0], %1;"
                 :: "r"(smem_mbar), "r"(TILE_BYTES) : "memory");
    asm volatile("cp.async.bulk.tensor.2d.shared::cta.global.tile.mbarrier::complete_tx::bytes "
                 "[%0], [%1, {%2, %3}], [%4];"
                 :: "r"(smem_tile), "l"(&in_map),
                    "r"(route * 64), "r"(row0), "r"(smem_mbar)
                 : "memory");

    // wait for TMA completion (phase parity 0)
    {
        uint32_t done;
        asm volatile(
            "{\n\t.reg .pred p;\n\t"
            "mbarrier.try_wait.parity.acquire.cta.shared::cta.b64 p, [%1], %2;\n\t"
            "selp.b32 %0, 1, 0, p;\n\t}"
            : "=r"(done) : "r"(smem_mbar), "r"(0u) : "memory");
        while (!done) {
            asm volatile(
                "{\n\t.reg .pred p;\n\t"
                "mbarrier.try_wait.parity.acquire.cta.shared::cta.b64 p, [%1], %2, 0x989680;\n\t"
                "selp.b32 %0, 1, 0, p;\n\t}"
                : "=r"(done) : "r"(smem_mbar), "r"(0u) : "memory");
        }
    }

    // bulk store: SMEM tile (packed, identical to output layout) -> GMEM
    float* dst = out + (long long)t * TILE_FLOATS;
    asm volatile("cp.async.bulk.global.shared::cta.bulk_group [%0], [%1], %2;"
                 :: "l"(dst), "r"(smem_tile), "r"(TILE_BYTES) : "memory");
    asm volatile("cp.async.bulk.commit_group;" ::: "memory");
    asm volatile("cp.async.bulk.wait_group 0;" ::: "memory");
}

extern "C" void kernel_launch(void* const* d_in, const int* in_sizes, int n_in,
                              void* d_out, int out_size)
{
    const float* in      = (const float*)d_in[0];
    const float* routing = (const float*)d_in[1];
    float*       out     = (float*)d_out;

    // Build the 2D tensor map host-side (driver entry point via runtime API,
    // so no -lcuda link dependency). Pure host work; graph-capture safe.
    typedef CUresult (*EncodeFn)(
        CUtensorMap*, CUtensorMapDataType, cuuint32_t, void*,
        const cuuint64_t*, const cuuint64_t*, const cuuint32_t*, const cuuint32_t*,
        CUtensorMapInterleave, CUtensorMapSwizzle, CUtensorMapL2promotion,
        CUtensorMapFloatOOBfill);
    void* fn_ptr = nullptr;
    cudaDriverEntryPointQueryResult qres;
    cudaGetDriverEntryPoint("cuTensorMapEncodeTiled", &fn_ptr,
                            cudaEnableDefault, &qres);
    EncodeFn encode = (EncodeFn)fn_ptr;

    CUtensorMap in_map;
    cuuint64_t dims[2]    = {256, (cuuint64_t)B * HW};     // inner floats, rows
    cuuint64_t strides[1] = {256 * sizeof(float)};         // 1024B row pitch
    cuuint32_t box[2]     = {64, ROWS_PER_TILE};           // 256B x 64 rows
    cuuint32_t estr[2]    = {1, 1};
    encode(&in_map, CU_TENSOR_MAP_DATA_TYPE_FLOAT32, 2, (void*)in,
           dims, strides, box, estr,
           CU_TENSOR_MAP_INTERLEAVE_NONE, CU_TENSOR_MAP_SWIZZLE_NONE,
           CU_TENSOR_MAP_L2_PROMOTION_L2_128B, CU_TENSOR_MAP_FLOAT_OOB_FILL_NONE);

    routing_tma_kernel<<<BLOCKS, 32>>>(in_map, routing, out);
}